// round 13
// baseline (speedup 1.0000x reference)
#include <cuda_runtime.h>

// ============================================================================
// Compile-time network machinery (all stages 0-1-verified at compile time).
//  - Batcher odd-even mergesort (power-of-2) + prefix restriction.
//  - Generalized odd-even merge on index lists (oem2).
//  - NEW: 4-address SSA compare-exchanges. Each merge renames the first write
//    of every input wire to a fresh slot, making merges non-destructive at
//    zero instruction cost -> ALL preserve-copies are eliminated.
//  - Per-merge exhaustive 0-1 verification runs on the RENAMED op list.
//  - Whole-program constexpr test: 16 pseudo-random input sets through the
//    final sliced program, all 8 outputs checked against a reference
//    selection-sort rank-12. Catches slot-lifetime/aliasing bugs.
//  - Interval pruning theorem: for rank-12 of union(A sorted 20, B sorted 5),
//    A[i] has union position in [i, i+5]; answer = index 5 of
//    sorted(A[7..12] u B).
// ============================================================================

struct P8 { unsigned char a, b; };
struct Op4 { unsigned char a, b, da, db, op; }; // reads a,b; writes da(min), db(max)
                                                // op: 0=both, 1=min-only, 2=max-only
struct CE3 { unsigned char a, b, op; };

constexpr void oem_merge(int lo, int n, int r, P8* out, int& cnt) {
    int m = r * 2;
    if (m < n) {
        oem_merge(lo,     n, m, out, cnt);
        oem_merge(lo + r, n, m, out, cnt);
        for (int i = lo + r; i + r < lo + n; i += m)
            out[cnt++] = P8{(unsigned char)i, (unsigned char)(i + r)};
    } else {
        out[cnt++] = P8{(unsigned char)lo, (unsigned char)(lo + r)};
    }
}

constexpr void oem_sort(int lo, int n, P8* out, int& cnt) {
    if (n > 1) {
        int m = n / 2;
        oem_sort(lo,     m, out, cnt);
        oem_sort(lo + m, m, out, cnt);
        oem_merge(lo, n, 1, out, cnt);
    }
}

// ---- sort-5 network: Batcher sort-8 restricted to slots < 5 (9 CEs).
struct Net5 { int n; P8 p[24]; };

constexpr Net5 build_sort5() {
    P8 all[64] = {};
    int cnt = 0;
    oem_sort(0, 8, all, cnt);
    Net5 s = {};
    for (int i = 0; i < cnt; ++i)
        if (all[i].a < 5 && all[i].b < 5)
            s.p[s.n++] = all[i];
    return s;
}

constexpr bool verify_sort5(const Net5& s) {
    for (int m = 0; m < 32; ++m) {
        int v[5] = {};
        for (int k = 0; k < 5; ++k) v[k] = (m >> k) & 1;
        for (int i = 0; i < s.n; ++i) {
            int a = s.p[i].a, b = s.p[i].b;
            if (v[a] > v[b]) { int t = v[a]; v[a] = v[b]; v[b] = t; }
        }
        for (int k = 0; k + 1 < 5; ++k)
            if (v[k] > v[k + 1]) return false;
    }
    return true;
}

static_assert(verify_sort5(build_sort5()), "sort5 network invalid");

// ---- Generalized odd-even merge on index lists (Knuth 5.2.2-style).
constexpr void oem2(const int* A, int m, const int* B, int n, int* Z,
                    P8* ce, int& cnt) {
    if (m == 0) { for (int i = 0; i < n; ++i) Z[i] = B[i]; return; }
    if (n == 0) { for (int i = 0; i < m; ++i) Z[i] = A[i]; return; }
    if (m == 1 && n == 1) {
        ce[cnt++] = P8{(unsigned char)A[0], (unsigned char)B[0]};
        Z[0] = A[0]; Z[1] = B[0];
        return;
    }
    int Ae[25] = {}, Ao[25] = {}, Be[25] = {}, Bo[25] = {};
    int nae = 0, nao = 0, nbe = 0, nbo = 0;
    for (int i = 0; i < m; ++i) { if (i & 1) Ao[nao++] = A[i]; else Ae[nae++] = A[i]; }
    for (int i = 0; i < n; ++i) { if (i & 1) Bo[nbo++] = B[i]; else Be[nbe++] = B[i]; }
    int E[25] = {}, O[25] = {};
    oem2(Ae, nae, Be, nbe, E, ce, cnt);
    oem2(Ao, nao, Bo, nbo, O, ce, cnt);
    int ne = nae + nbe, no = nao + nbo;
    Z[0] = E[0];
    int zi = 1;
    int i = 0;
    for (; i < no && i + 1 < ne; ++i) {
        ce[cnt++] = P8{(unsigned char)O[i], (unsigned char)E[i + 1]};
        Z[zi++] = O[i];
        Z[zi++] = E[i + 1];
    }
    for (; i < no; ++i) Z[zi++] = O[i];
    for (int j = i + 1; j < ne; ++j) Z[zi++] = E[j];
}

// ---- Boundary network: sort-25 sliced for {12,13} with op-level pruning.
struct Net { int n; CE3 p[256]; };

constexpr Net slice_net25(const P8* ce, int cnt, const bool* outputs_needed) {
    bool need[25] = {};
    for (int i = 0; i < 25; ++i) need[i] = outputs_needed[i];
    signed char op[256] = {};
    bool keep[256] = {};
    for (int i = cnt - 1; i >= 0; --i) {
        bool na = need[ce[i].a], nb = need[ce[i].b];
        if (!na && !nb) continue;
        keep[i] = true;
        op[i] = (na && nb) ? 0 : (na ? 1 : 2);
        need[ce[i].a] = true;
        need[ce[i].b] = true;
    }
    Net net = {};
    for (int i = 0; i < cnt; ++i)
        if (keep[i])
            net.p[net.n++] = CE3{ce[i].a, ce[i].b, (unsigned char)op[i]};
    return net;
}

constexpr Net build_boundary_net() {
    P8 all[256] = {};
    int cnt = 0;
    oem_sort(0, 32, all, cnt);
    P8 filt[256] = {};
    int fc = 0;
    for (int i = 0; i < cnt; ++i)
        if (all[i].a < 25 && all[i].b < 25)
            filt[fc++] = all[i];
    bool outs[25] = {};
    outs[12] = true;
    outs[13] = true;
    return slice_net25(filt, fc, outs);
}

__device__ constexpr Net BNET = build_boundary_net();

// ---- SSA emission helpers ---------------------------------------------------

// Exhaustive 0-1 verification of one RENAMED merge stage over 256 slots.
constexpr bool verify4(const Op4* ops, int ibeg, int iend,
                       const int* A, int m, const int* B, int n,
                       const int* Z) {
    for (int i = 0; i <= m; ++i) {
        for (int j = 0; j <= n; ++j) {
            int v[256] = {};
            for (int k = 0; k < m; ++k) v[A[k]] = (k >= m - i) ? 1 : 0;
            for (int k = 0; k < n; ++k) v[B[k]] = (k >= n - j) ? 1 : 0;
            for (int t = ibeg; t < iend; ++t) {
                int va = v[ops[t].a], vb = v[ops[t].b];
                int mn = va < vb ? va : vb;
                int mx = va < vb ? vb : va;
                v[ops[t].da] = mn;
                v[ops[t].db] = mx;
            }
            for (int k = 0; k + 1 < m + n; ++k)
                if (v[Z[k]] > v[Z[k + 1]]) return false;
        }
    }
    return true;
}

constexpr void emit_sortcol(int j, Op4* ops, int& oc) {
    Net5 s5 = build_sort5();
    for (int i = 0; i < s5.n; ++i) {
        unsigned char a = (unsigned char)(5 * j + s5.p[i].a);
        unsigned char b = (unsigned char)(5 * j + s5.p[i].b);
        ops[oc++] = Op4{a, b, a, b, 0};          // in-place (raw loads, no reuse)
    }
}

// SSA merge: first write of each input wire goes to a fresh slot from
// [freshbase, ...), so all input slots survive. Verified post-rename.
constexpr void emit_merge4(const int* A, int m, const int* B, int n,
                           int* Zout, int freshbase,
                           Op4* ops, int& oc, bool& ok) {
    int Z[25] = {};
    P8 ce[160] = {};
    int cc = 0;
    oem2(A, m, B, n, Z, ce, cc);

    int M[256] = {};
    for (int i = 0; i < 256; ++i) M[i] = i;
    int fresh = freshbase;
    int begin = oc;
    for (int i = 0; i < cc; ++i) {
        int oa = ce[i].a, ob = ce[i].b;
        int ra = M[oa], rb = M[ob];
        int da = 0, db = 0;
        if (ra == oa) { da = fresh; M[oa] = fresh; ++fresh; } else { da = ra; }
        if (rb == ob) { db = fresh; M[ob] = fresh; ++fresh; } else { db = rb; }
        ops[oc++] = Op4{(unsigned char)ra, (unsigned char)rb,
                        (unsigned char)da, (unsigned char)db, 0};
    }
    for (int k = 0; k < m + n; ++k) Zout[k] = M[Z[k]];
    ok = ok && verify4(ops, begin, oc, A, m, B, n, Zout);
}

// ---- Global interior program, 8 pixels per thread, SSA slots.
// 0..59: columns c0..c11 (col j at 5j..5j+4), sorted in place.
// Fresh regions (disjoint lifetimes, hand-laid + machine-tested):
//   pairs: 60..69 (reused x3), 70..79 (reused x2)
//   quads: QA 80..99, QB 122..141, QC 164..183, QD 206..225
//   finals: F0 100, F1 111, F2 142, F3 153, F4 184, F5 195, F6 226, F7 237
struct Prog { int n; Op4 p[460]; unsigned char outslot[8]; bool ok; };

constexpr Prog build_prog() {
    Op4 ops[460] = {};
    int oc = 0;
    bool ok = true;

    int C[12][5] = {};
    for (int j = 0; j < 12; ++j)
        for (int k = 0; k < 5; ++k) C[j][k] = 5 * j + k;

    int Z12[25] = {}, Z34[25] = {}, Z56[25] = {}, Z78[25] = {}, Z910[25] = {};
    int QA[25] = {}, QB[25] = {}, QC[25] = {}, QD[25] = {};
    unsigned char outs[8] = {};

    // ---- Stage A: cols 0..4, quad A, px0, px1.
    emit_sortcol(0, ops, oc);
    emit_sortcol(1, ops, oc);
    emit_sortcol(2, ops, oc);
    emit_sortcol(3, ops, oc);
    emit_sortcol(4, ops, oc);
    emit_merge4(C[1], 5, C[2], 5, Z12, 60, ops, oc, ok);
    emit_merge4(C[3], 5, C[4], 5, Z34, 70, ops, oc, ok);
    emit_merge4(Z12, 10, Z34, 10, QA, 80, ops, oc, ok);
    int A1[6] = {};
    for (int k = 0; k < 6; ++k) A1[k] = QA[7 + k];
    {
        int ZF[25] = {};                              // px0 = rank5(QAwin u c0)
        emit_merge4(A1, 6, C[0], 5, ZF, 100, ops, oc, ok);
        outs[0] = (unsigned char)ZF[5];
    }
    emit_sortcol(5, ops, oc);
    {
        int ZF[25] = {};                              // px1 = rank5(QAwin u c5)
        emit_merge4(A1, 6, C[5], 5, ZF, 111, ops, oc, ok);
        outs[1] = (unsigned char)ZF[5];
    }

    // ---- Stage B: col 6, quad B, px2, px3.
    emit_sortcol(6, ops, oc);
    emit_merge4(C[5], 5, C[6], 5, Z56, 60, ops, oc, ok);   // reuse (Z12 dead)
    emit_merge4(Z34, 10, Z56, 10, QB, 122, ops, oc, ok);
    int A3[6] = {};
    for (int k = 0; k < 6; ++k) A3[k] = QB[7 + k];
    {
        int ZF[25] = {};                              // px2 = rank5(QBwin u c2)
        emit_merge4(A3, 6, C[2], 5, ZF, 142, ops, oc, ok);
        outs[2] = (unsigned char)ZF[5];
    }
    emit_sortcol(7, ops, oc);
    {
        int ZF[25] = {};                              // px3 = rank5(QBwin u c7)
        emit_merge4(A3, 6, C[7], 5, ZF, 153, ops, oc, ok);
        outs[3] = (unsigned char)ZF[5];
    }

    // ---- Stage C: col 8, quad C, px4, px5.
    emit_sortcol(8, ops, oc);
    emit_merge4(C[7], 5, C[8], 5, Z78, 70, ops, oc, ok);   // reuse (Z34 dead)
    emit_merge4(Z56, 10, Z78, 10, QC, 164, ops, oc, ok);
    int A5[6] = {};
    for (int k = 0; k < 6; ++k) A5[k] = QC[7 + k];
    {
        int ZF[25] = {};                              // px4 = rank5(QCwin u c4)
        emit_merge4(A5, 6, C[4], 5, ZF, 184, ops, oc, ok);
        outs[4] = (unsigned char)ZF[5];
    }
    emit_sortcol(9, ops, oc);
    {
        int ZF[25] = {};                              // px5 = rank5(QCwin u c9)
        emit_merge4(A5, 6, C[9], 5, ZF, 195, ops, oc, ok);
        outs[5] = (unsigned char)ZF[5];
    }

    // ---- Stage D: col 10, quad D, px6, px7.
    emit_sortcol(10, ops, oc);
    emit_merge4(C[9], 5, C[10], 5, Z910, 60, ops, oc, ok); // reuse (Z56 dead)
    emit_merge4(Z78, 10, Z910, 10, QD, 206, ops, oc, ok);
    int A7[6] = {};
    for (int k = 0; k < 6; ++k) A7[k] = QD[7 + k];
    {
        int ZF[25] = {};                              // px6 = rank5(QDwin u c6)
        emit_merge4(A7, 6, C[6], 5, ZF, 226, ops, oc, ok);
        outs[6] = (unsigned char)ZF[5];
    }
    emit_sortcol(11, ops, oc);
    {
        int ZF[25] = {};                              // px7 = rank5(QDwin u c11)
        emit_merge4(A7, 6, C[11], 5, ZF, 237, ops, oc, ok);
        outs[7] = (unsigned char)ZF[5];
    }

    // ---- Global backward slice with op-level pruning (4-address form).
    bool need[256] = {};
    for (int i = 0; i < 8; ++i) need[outs[i]] = true;
    bool keep[460] = {};
    unsigned char opc[460] = {};
    for (int i = oc - 1; i >= 0; --i) {
        bool na = need[ops[i].da], nb = need[ops[i].db];
        if (!na && !nb) continue;
        keep[i] = true;
        opc[i] = (na && nb) ? 0 : (na ? 1 : 2);
        if (na) need[ops[i].da] = false;          // written here
        if (nb) need[ops[i].db] = false;
        need[ops[i].a] = true;                    // read here
        need[ops[i].b] = true;
    }

    Prog pr = {};
    pr.ok = ok;
    for (int i = 0; i < oc; ++i)
        if (keep[i]) {
            pr.p[pr.n] = ops[i];
            pr.p[pr.n].op = opc[i];
            ++pr.n;
        }
    for (int i = 0; i < 8; ++i) pr.outslot[i] = outs[i];
    return pr;
}

// Whole-program randomized check of the SLICED program against a reference
// selection-sort rank-12 (catches lifetime/aliasing/slice bugs end-to-end).
constexpr bool test_prog(const Prog& pr) {
    unsigned int seed = 12345u;
    for (int trial = 0; trial < 16; ++trial) {
        int v[256] = {};
        int in[60] = {};
        for (int i = 0; i < 60; ++i) {
            seed = seed * 1664525u + 1013904223u;
            in[i] = (int)(seed >> 16) - 32768;
            v[i] = in[i];
        }
        for (int i = 0; i < pr.n; ++i) {
            int va = v[pr.p[i].a], vb = v[pr.p[i].b];
            int mn = va < vb ? va : vb;
            int mx = va < vb ? vb : va;
            if (pr.p[i].op == 0) { v[pr.p[i].da] = mn; v[pr.p[i].db] = mx; }
            else if (pr.p[i].op == 1) { v[pr.p[i].da] = mn; }
            else { v[pr.p[i].db] = mx; }
        }
        for (int j = 0; j < 8; ++j) {
            int cand[25] = {};
            for (int col = 0; col < 5; ++col)
                for (int k = 0; k < 5; ++k)
                    cand[col * 5 + k] = in[5 * (j + col) + k];
            for (int s = 0; s <= 12; ++s) {
                int m = s;
                for (int t2 = s + 1; t2 < 25; ++t2)
                    if (cand[t2] < cand[m]) m = t2;
                int tmp = cand[s]; cand[s] = cand[m]; cand[m] = tmp;
            }
            if (v[pr.outslot[j]] != cand[12]) return false;
        }
    }
    return true;
}

__device__ constexpr Prog PROG = build_prog();
static_assert(build_prog().ok, "per-stage merge verification failed");
static_assert(build_prog().n <= 460, "program overflow");
static_assert(test_prog(build_prog()), "whole-program median check failed");

// ============================================================================
// Fused kernel
// ============================================================================

#define MF_C 3
#define MF_H 1024
#define MF_W 1024

// Boundary: 13272 px/channel (rows 0-1, rows 1021-1023, plus cols
// {0,1,1018..1023} of rows 2..1020) -> 39816 px -> 312 blocks of 128.
// Interior: 127 chunks x 1019 rows x 3 channels -> 3057 blocks; thread t
// covers x = 8t+2 .. 8t+9.
#define NB_BOUND 312
#define NB_INNER 3057

__global__ __launch_bounds__(128)
void median_fused(const float* __restrict__ img, float* __restrict__ out) {
    constexpr int H = MF_H, W = MF_W;
    int blk = blockIdx.x;

    if (blk >= NB_BOUND) {
        // -------------------- Interior path --------------------
        int ib = blk - NB_BOUND;                 // 0 .. 3056
        int yrow = ib % 1019;
        int c = ib / 1019;
        int t = threadIdx.x;
        if (t >= 127) return;
        int y = yrow + 2;

        const float* base = img + ((size_t)c << 20) + (size_t)(y - 2) * W + 8 * t;

        float w[248];
#pragma unroll
        for (int k = 0; k < 5; ++k) {
            float4 a = *reinterpret_cast<const float4*>(base + (size_t)k * W);
            float4 b = *reinterpret_cast<const float4*>(base + (size_t)k * W + 4);
            float4 d = *reinterpret_cast<const float4*>(base + (size_t)k * W + 8);
            w[0 + k]  = a.x; w[5 + k]  = a.y; w[10 + k] = a.z; w[15 + k] = a.w;
            w[20 + k] = b.x; w[25 + k] = b.y; w[30 + k] = b.z; w[35 + k] = b.w;
            w[40 + k] = d.x; w[45 + k] = d.y; w[50 + k] = d.z; w[55 + k] = d.w;
        }

        // Unified sliced SSA program.
#pragma unroll
        for (int i = 0; i < PROG.n; ++i) {
            const int a  = PROG.p[i].a,  b  = PROG.p[i].b;
            const int da = PROG.p[i].da, db = PROG.p[i].db;
            const int op = PROG.p[i].op;
            if (op == 0) {
                float mn = fminf(w[a], w[b]);
                float mx = fmaxf(w[a], w[b]);
                w[da] = mn;
                w[db] = mx;
            } else if (op == 1) {
                w[da] = fminf(w[a], w[b]);
            } else {
                w[db] = fmaxf(w[a], w[b]);
            }
        }

        int x0 = 8 * t + 2;
        float* orow = out + ((size_t)c << 20) + (size_t)y * W;

        // x0 is even -> 8-byte aligned float2 stores.
#pragma unroll
        for (int p = 0; p < 4; ++p) {
            float2 s;
            s.x = w[PROG.outslot[2 * p]];
            s.y = w[PROG.outslot[2 * p + 1]];
            *reinterpret_cast<float2*>(orow + x0 + 2 * p) = s;
        }
        return;
    }

    // -------------------- Boundary path --------------------
    int idx = blk * 128 + threadIdx.x;           // 0 .. 39935
    if (idx >= 3 * 13272) return;
    int c = idx / 13272;
    int b = idx - c * 13272;

    int y, x;
    if (b < 2048) {                     // rows 0..1
        y = b >> 10; x = b & 1023;
    } else if (b < 5120) {              // rows 1021..1023
        int r = b - 2048; y = 1021 + (r >> 10); x = r & 1023;
    } else {                            // rows 2..1020, cols {0,1,1018..1023}
        int r = b - 5120;
        int q = r >> 3;
        int s = r & 7;
        y = 2 + q;
        x = (s < 2) ? s : 1016 + s;
    }

    const float* cimg = img + ((size_t)c << 20);

    float v[25];
    int inv = 0;

#pragma unroll
    for (int ky = 0; ky < 5; ++ky) {
        int yy = y + ky - 2;
        bool vy = (yy >= 0) && (yy <= H - 2);
        int  yc = min(max(yy, 0), H - 1);
        const float* row = cimg + (size_t)yc * W;
#pragma unroll
        for (int kx = 0; kx < 5; ++kx) {
            int xx = x + kx - 2;
            bool vx = (xx >= 0) && (xx <= W - 2);
            int  xc = min(max(xx, 0), W - 1);
            float val = __ldg(row + xc);
            if (!(vy && vx)) {
                val = __int_as_float((inv & 1) ? 0x7f800000u : 0xff800000u);
                ++inv;
            }
            v[ky * 5 + kx] = val;
        }
    }

#pragma unroll
    for (int i = 0; i < BNET.n; ++i) {
        const int a = BNET.p[i].a, b2 = BNET.p[i].b;
        const int op = BNET.p[i].op;
        if (op == 0) {
            float mn = fminf(v[a], v[b2]);
            float mx = fmaxf(v[a], v[b2]);
            v[a] = mn;
            v[b2] = mx;
        } else if (op == 1) {
            v[a] = fminf(v[a], v[b2]);
        } else {
            v[b2] = fmaxf(v[a], v[b2]);
        }
    }

    float s12 = v[12];
    float s13 = v[13];
    float hi  = (inv & 1) ? s13 : s12;
    out[((size_t)c << 20) + (size_t)y * W + x] = 0.5f * (s12 + hi);
}

extern "C" void kernel_launch(void* const* d_in, const int* in_sizes, int n_in,
                              void* d_out, int out_size) {
    const float* img = (const float*)d_in[0];
    float* out = (float*)d_out;
    median_fused<<<NB_BOUND + NB_INNER, 128>>>(img, out);
}

// round 14
// speedup vs baseline: 1.0328x; 1.0328x over previous
#include <cuda_runtime.h>

// ============================================================================
// Compile-time network machinery (all stages 0-1-verified at compile time).
//  - Batcher odd-even mergesort (power-of-2) + prefix restriction.
//  - Generalized odd-even merge on index lists (oem2).
//  - 4-address SSA compare-exchanges (merges non-destructive, zero copies).
//  - Per-merge exhaustive 0-1 verification on the RENAMED op list.
//  - Whole-program constexpr test vs reference selection-sort rank-12.
//  - NEW: execution SPLIT after px3. Kernel stores px0..3 mid-body, then
//    loads cols 8..11 and finishes px4..7 -> halves peak register liveness,
//    eliminating ptxas spills at its 60-reg occupancy target.
//  - Interval pruning theorem: rank-12 of union(A sorted 20, B sorted 5) =
//    index 5 of sorted(A[7..12] u B).
// ============================================================================

struct P8 { unsigned char a, b; };
struct Op4 { unsigned char a, b, da, db, op; }; // reads a,b; writes da(min), db(max)
struct CE3 { unsigned char a, b, op; };

constexpr void oem_merge(int lo, int n, int r, P8* out, int& cnt) {
    int m = r * 2;
    if (m < n) {
        oem_merge(lo,     n, m, out, cnt);
        oem_merge(lo + r, n, m, out, cnt);
        for (int i = lo + r; i + r < lo + n; i += m)
            out[cnt++] = P8{(unsigned char)i, (unsigned char)(i + r)};
    } else {
        out[cnt++] = P8{(unsigned char)lo, (unsigned char)(lo + r)};
    }
}

constexpr void oem_sort(int lo, int n, P8* out, int& cnt) {
    if (n > 1) {
        int m = n / 2;
        oem_sort(lo,     m, out, cnt);
        oem_sort(lo + m, m, out, cnt);
        oem_merge(lo, n, 1, out, cnt);
    }
}

// ---- sort-5 network: Batcher sort-8 restricted to slots < 5 (9 CEs).
struct Net5 { int n; P8 p[24]; };

constexpr Net5 build_sort5() {
    P8 all[64] = {};
    int cnt = 0;
    oem_sort(0, 8, all, cnt);
    Net5 s = {};
    for (int i = 0; i < cnt; ++i)
        if (all[i].a < 5 && all[i].b < 5)
            s.p[s.n++] = all[i];
    return s;
}

constexpr bool verify_sort5(const Net5& s) {
    for (int m = 0; m < 32; ++m) {
        int v[5] = {};
        for (int k = 0; k < 5; ++k) v[k] = (m >> k) & 1;
        for (int i = 0; i < s.n; ++i) {
            int a = s.p[i].a, b = s.p[i].b;
            if (v[a] > v[b]) { int t = v[a]; v[a] = v[b]; v[b] = t; }
        }
        for (int k = 0; k + 1 < 5; ++k)
            if (v[k] > v[k + 1]) return false;
    }
    return true;
}

static_assert(verify_sort5(build_sort5()), "sort5 network invalid");

// ---- Generalized odd-even merge on index lists (Knuth 5.2.2-style).
constexpr void oem2(const int* A, int m, const int* B, int n, int* Z,
                    P8* ce, int& cnt) {
    if (m == 0) { for (int i = 0; i < n; ++i) Z[i] = B[i]; return; }
    if (n == 0) { for (int i = 0; i < m; ++i) Z[i] = A[i]; return; }
    if (m == 1 && n == 1) {
        ce[cnt++] = P8{(unsigned char)A[0], (unsigned char)B[0]};
        Z[0] = A[0]; Z[1] = B[0];
        return;
    }
    int Ae[25] = {}, Ao[25] = {}, Be[25] = {}, Bo[25] = {};
    int nae = 0, nao = 0, nbe = 0, nbo = 0;
    for (int i = 0; i < m; ++i) { if (i & 1) Ao[nao++] = A[i]; else Ae[nae++] = A[i]; }
    for (int i = 0; i < n; ++i) { if (i & 1) Bo[nbo++] = B[i]; else Be[nbe++] = B[i]; }
    int E[25] = {}, O[25] = {};
    oem2(Ae, nae, Be, nbe, E, ce, cnt);
    oem2(Ao, nao, Bo, nbo, O, ce, cnt);
    int ne = nae + nbe, no = nao + nbo;
    Z[0] = E[0];
    int zi = 1;
    int i = 0;
    for (; i < no && i + 1 < ne; ++i) {
        ce[cnt++] = P8{(unsigned char)O[i], (unsigned char)E[i + 1]};
        Z[zi++] = O[i];
        Z[zi++] = E[i + 1];
    }
    for (; i < no; ++i) Z[zi++] = O[i];
    for (int j = i + 1; j < ne; ++j) Z[zi++] = E[j];
}

// ---- Boundary network: sort-25 sliced for {12,13} with op-level pruning.
struct Net { int n; CE3 p[256]; };

constexpr Net slice_net25(const P8* ce, int cnt, const bool* outputs_needed) {
    bool need[25] = {};
    for (int i = 0; i < 25; ++i) need[i] = outputs_needed[i];
    signed char op[256] = {};
    bool keep[256] = {};
    for (int i = cnt - 1; i >= 0; --i) {
        bool na = need[ce[i].a], nb = need[ce[i].b];
        if (!na && !nb) continue;
        keep[i] = true;
        op[i] = (na && nb) ? 0 : (na ? 1 : 2);
        need[ce[i].a] = true;
        need[ce[i].b] = true;
    }
    Net net = {};
    for (int i = 0; i < cnt; ++i)
        if (keep[i])
            net.p[net.n++] = CE3{ce[i].a, ce[i].b, (unsigned char)op[i]};
    return net;
}

constexpr Net build_boundary_net() {
    P8 all[256] = {};
    int cnt = 0;
    oem_sort(0, 32, all, cnt);
    P8 filt[256] = {};
    int fc = 0;
    for (int i = 0; i < cnt; ++i)
        if (all[i].a < 25 && all[i].b < 25)
            filt[fc++] = all[i];
    bool outs[25] = {};
    outs[12] = true;
    outs[13] = true;
    return slice_net25(filt, fc, outs);
}

__device__ constexpr Net BNET = build_boundary_net();

// ---- SSA emission helpers ---------------------------------------------------

constexpr bool verify4(const Op4* ops, int ibeg, int iend,
                       const int* A, int m, const int* B, int n,
                       const int* Z) {
    for (int i = 0; i <= m; ++i) {
        for (int j = 0; j <= n; ++j) {
            int v[256] = {};
            for (int k = 0; k < m; ++k) v[A[k]] = (k >= m - i) ? 1 : 0;
            for (int k = 0; k < n; ++k) v[B[k]] = (k >= n - j) ? 1 : 0;
            for (int t = ibeg; t < iend; ++t) {
                int va = v[ops[t].a], vb = v[ops[t].b];
                int mn = va < vb ? va : vb;
                int mx = va < vb ? vb : va;
                v[ops[t].da] = mn;
                v[ops[t].db] = mx;
            }
            for (int k = 0; k + 1 < m + n; ++k)
                if (v[Z[k]] > v[Z[k + 1]]) return false;
        }
    }
    return true;
}

constexpr void emit_sortcol(int j, Op4* ops, int& oc) {
    Net5 s5 = build_sort5();
    for (int i = 0; i < s5.n; ++i) {
        unsigned char a = (unsigned char)(5 * j + s5.p[i].a);
        unsigned char b = (unsigned char)(5 * j + s5.p[i].b);
        ops[oc++] = Op4{a, b, a, b, 0};          // in-place (raw loads, no reuse)
    }
}

// SSA merge: first write of each input wire goes to a fresh slot, so all
// input slots survive. Verified post-rename.
constexpr void emit_merge4(const int* A, int m, const int* B, int n,
                           int* Zout, int freshbase,
                           Op4* ops, int& oc, bool& ok) {
    int Z[25] = {};
    P8 ce[160] = {};
    int cc = 0;
    oem2(A, m, B, n, Z, ce, cc);

    int M[256] = {};
    for (int i = 0; i < 256; ++i) M[i] = i;
    int fresh = freshbase;
    int begin = oc;
    for (int i = 0; i < cc; ++i) {
        int oa = ce[i].a, ob = ce[i].b;
        int ra = M[oa], rb = M[ob];
        int da = 0, db = 0;
        if (ra == oa) { da = fresh; M[oa] = fresh; ++fresh; } else { da = ra; }
        if (rb == ob) { db = fresh; M[ob] = fresh; ++fresh; } else { db = rb; }
        ops[oc++] = Op4{(unsigned char)ra, (unsigned char)rb,
                        (unsigned char)da, (unsigned char)db, 0};
    }
    for (int k = 0; k < m + n; ++k) Zout[k] = M[Z[k]];
    ok = ok && verify4(ops, begin, oc, A, m, B, n, Zout);
}

// ---- Global interior program, 8 pixels per thread, SSA slots, split exec.
// 0..59: columns c0..c11 (col j at 5j..5j+4), sorted in place.
// Fresh regions: pairs 60..69 (x3), 70..79 (x2); quads QA 80, QB 122,
// QC 164, QD 206; finals F0 100, F1 111, F2 142, F3 153, F4 184, F5 195,
// F6 226, F7 237. Output F-regions are never reused.
struct Prog { int n; int split; Op4 p[460]; unsigned char outslot[8]; bool ok; };

constexpr Prog build_prog() {
    Op4 ops[460] = {};
    int oc = 0;
    bool ok = true;

    int C[12][5] = {};
    for (int j = 0; j < 12; ++j)
        for (int k = 0; k < 5; ++k) C[j][k] = 5 * j + k;

    int Z12[25] = {}, Z34[25] = {}, Z56[25] = {}, Z78[25] = {}, Z910[25] = {};
    int QA[25] = {}, QB[25] = {}, QC[25] = {}, QD[25] = {};
    unsigned char outs[8] = {};

    // ---- First half: cols 0..7, px0..px3.
    emit_sortcol(0, ops, oc);
    emit_sortcol(1, ops, oc);
    emit_sortcol(2, ops, oc);
    emit_sortcol(3, ops, oc);
    emit_sortcol(4, ops, oc);
    emit_merge4(C[1], 5, C[2], 5, Z12, 60, ops, oc, ok);
    emit_merge4(C[3], 5, C[4], 5, Z34, 70, ops, oc, ok);
    emit_merge4(Z12, 10, Z34, 10, QA, 80, ops, oc, ok);
    int A1[6] = {};
    for (int k = 0; k < 6; ++k) A1[k] = QA[7 + k];
    {
        int ZF[25] = {};                              // px0 = rank5(QAwin u c0)
        emit_merge4(A1, 6, C[0], 5, ZF, 100, ops, oc, ok);
        outs[0] = (unsigned char)ZF[5];
    }
    emit_sortcol(5, ops, oc);
    {
        int ZF[25] = {};                              // px1 = rank5(QAwin u c5)
        emit_merge4(A1, 6, C[5], 5, ZF, 111, ops, oc, ok);
        outs[1] = (unsigned char)ZF[5];
    }
    emit_sortcol(6, ops, oc);
    emit_merge4(C[5], 5, C[6], 5, Z56, 60, ops, oc, ok);   // reuse (Z12 dead)
    emit_merge4(Z34, 10, Z56, 10, QB, 122, ops, oc, ok);
    int A3[6] = {};
    for (int k = 0; k < 6; ++k) A3[k] = QB[7 + k];
    {
        int ZF[25] = {};                              // px2 = rank5(QBwin u c2)
        emit_merge4(A3, 6, C[2], 5, ZF, 142, ops, oc, ok);
        outs[2] = (unsigned char)ZF[5];
    }
    emit_sortcol(7, ops, oc);
    {
        int ZF[25] = {};                              // px3 = rank5(QBwin u c7)
        emit_merge4(A3, 6, C[7], 5, ZF, 153, ops, oc, ok);
        outs[3] = (unsigned char)ZF[5];
    }
    int split_raw = oc;                               // <- store px0..3 here

    // ---- Second half: cols 8..11, px4..px7.
    emit_sortcol(8, ops, oc);
    emit_merge4(C[7], 5, C[8], 5, Z78, 70, ops, oc, ok);   // reuse (Z34 dead)
    emit_merge4(Z56, 10, Z78, 10, QC, 164, ops, oc, ok);
    int A5[6] = {};
    for (int k = 0; k < 6; ++k) A5[k] = QC[7 + k];
    {
        int ZF[25] = {};                              // px4 = rank5(QCwin u c4)
        emit_merge4(A5, 6, C[4], 5, ZF, 184, ops, oc, ok);
        outs[4] = (unsigned char)ZF[5];
    }
    emit_sortcol(9, ops, oc);
    {
        int ZF[25] = {};                              // px5 = rank5(QCwin u c9)
        emit_merge4(A5, 6, C[9], 5, ZF, 195, ops, oc, ok);
        outs[5] = (unsigned char)ZF[5];
    }
    emit_sortcol(10, ops, oc);
    emit_merge4(C[9], 5, C[10], 5, Z910, 60, ops, oc, ok); // reuse (Z56 dead)
    emit_merge4(Z78, 10, Z910, 10, QD, 206, ops, oc, ok);
    int A7[6] = {};
    for (int k = 0; k < 6; ++k) A7[k] = QD[7 + k];
    {
        int ZF[25] = {};                              // px6 = rank5(QDwin u c6)
        emit_merge4(A7, 6, C[6], 5, ZF, 226, ops, oc, ok);
        outs[6] = (unsigned char)ZF[5];
    }
    emit_sortcol(11, ops, oc);
    {
        int ZF[25] = {};                              // px7 = rank5(QDwin u c11)
        emit_merge4(A7, 6, C[11], 5, ZF, 237, ops, oc, ok);
        outs[7] = (unsigned char)ZF[5];
    }

    // ---- Global backward slice with op-level pruning (4-address form).
    bool need[256] = {};
    for (int i = 0; i < 8; ++i) need[outs[i]] = true;
    bool keep[460] = {};
    unsigned char opc[460] = {};
    for (int i = oc - 1; i >= 0; --i) {
        bool na = need[ops[i].da], nb = need[ops[i].db];
        if (!na && !nb) continue;
        keep[i] = true;
        opc[i] = (na && nb) ? 0 : (na ? 1 : 2);
        if (na) need[ops[i].da] = false;          // written here
        if (nb) need[ops[i].db] = false;
        need[ops[i].a] = true;                    // read here
        need[ops[i].b] = true;
    }

    Prog pr = {};
    pr.ok = ok;
    for (int i = 0; i < oc; ++i)
        if (keep[i]) {
            if (i < split_raw) ++pr.split;        // remap split through slice
            pr.p[pr.n] = ops[i];
            pr.p[pr.n].op = opc[i];
            ++pr.n;
        }
    for (int i = 0; i < 8; ++i) pr.outslot[i] = outs[i];
    return pr;
}

// Whole-program randomized check of the SLICED program against a reference
// selection-sort rank-12 (catches lifetime/aliasing/slice/split bugs).
constexpr bool test_prog(const Prog& pr) {
    unsigned int seed = 12345u;
    for (int trial = 0; trial < 16; ++trial) {
        int v[256] = {};
        int in[60] = {};
        for (int i = 0; i < 60; ++i) {
            seed = seed * 1664525u + 1013904223u;
            in[i] = (int)(seed >> 16) - 32768;
            v[i] = in[i];
        }
        int snap[4] = {};
        for (int i = 0; i < pr.n; ++i) {
            if (i == pr.split)                     // emulate mid-kernel store
                for (int j = 0; j < 4; ++j) snap[j] = v[pr.outslot[j]];
            int va = v[pr.p[i].a], vb = v[pr.p[i].b];
            int mn = va < vb ? va : vb;
            int mx = va < vb ? vb : va;
            if (pr.p[i].op == 0) { v[pr.p[i].da] = mn; v[pr.p[i].db] = mx; }
            else if (pr.p[i].op == 1) { v[pr.p[i].da] = mn; }
            else { v[pr.p[i].db] = mx; }
        }
        for (int j = 0; j < 8; ++j) {
            int cand[25] = {};
            for (int col = 0; col < 5; ++col)
                for (int k = 0; k < 5; ++k)
                    cand[col * 5 + k] = in[5 * (j + col) + k];
            for (int s = 0; s <= 12; ++s) {
                int m = s;
                for (int t2 = s + 1; t2 < 25; ++t2)
                    if (cand[t2] < cand[m]) m = t2;
                int tmp = cand[s]; cand[s] = cand[m]; cand[m] = tmp;
            }
            int got = (j < 4) ? snap[j] : v[pr.outslot[j]];
            if (got != cand[12]) return false;
        }
    }
    return true;
}

__device__ constexpr Prog PROG = build_prog();
static_assert(build_prog().ok, "per-stage merge verification failed");
static_assert(build_prog().n <= 460, "program overflow");
static_assert(build_prog().split > 0 && build_prog().split < build_prog().n,
              "bad split");
static_assert(test_prog(build_prog()), "whole-program median check failed");

// ============================================================================
// Fused kernel
// ============================================================================

#define MF_C 3
#define MF_H 1024
#define MF_W 1024

// Boundary: 13272 px/channel -> 39816 px -> 312 blocks of 128.
// Interior: 127 chunks x 1019 rows x 3 channels -> 3057 blocks; thread t
// covers x = 8t+2 .. 8t+9.
#define NB_BOUND 312
#define NB_INNER 3057

__global__ __launch_bounds__(128)
void median_fused(const float* __restrict__ img, float* __restrict__ out) {
    constexpr int H = MF_H, W = MF_W;
    int blk = blockIdx.x;

    if (blk >= NB_BOUND) {
        // -------------------- Interior path --------------------
        int ib = blk - NB_BOUND;                 // 0 .. 3056
        int yrow = ib % 1019;
        int c = ib / 1019;
        int t = threadIdx.x;
        if (t >= 127) return;
        int y = yrow + 2;

        const float* base = img + ((size_t)c << 20) + (size_t)(y - 2) * W + 8 * t;
        float* orow = out + ((size_t)c << 20) + (size_t)y * W;
        int x0 = 8 * t + 2;

        float w[248];

        // First half: load cols 0..7 only.
#pragma unroll
        for (int k = 0; k < 5; ++k) {
            float4 a = *reinterpret_cast<const float4*>(base + (size_t)k * W);
            float4 b = *reinterpret_cast<const float4*>(base + (size_t)k * W + 4);
            w[0 + k]  = a.x; w[5 + k]  = a.y; w[10 + k] = a.z; w[15 + k] = a.w;
            w[20 + k] = b.x; w[25 + k] = b.y; w[30 + k] = b.z; w[35 + k] = b.w;
        }

#pragma unroll
        for (int i = 0; i < PROG.split; ++i) {
            const int a  = PROG.p[i].a,  b  = PROG.p[i].b;
            const int da = PROG.p[i].da, db = PROG.p[i].db;
            const int op = PROG.p[i].op;
            if (op == 0) {
                float mn = fminf(w[a], w[b]);
                float mx = fmaxf(w[a], w[b]);
                w[da] = mn;
                w[db] = mx;
            } else if (op == 1) {
                w[da] = fminf(w[a], w[b]);
            } else {
                w[db] = fmaxf(w[a], w[b]);
            }
        }

        // Store px0..3 now -> their values (and much of the first half's
        // live set) die here, halving peak register liveness.
        {
            float2 s0, s1;
            s0.x = w[PROG.outslot[0]]; s0.y = w[PROG.outslot[1]];
            s1.x = w[PROG.outslot[2]]; s1.y = w[PROG.outslot[3]];
            *reinterpret_cast<float2*>(orow + x0)     = s0;
            *reinterpret_cast<float2*>(orow + x0 + 2) = s1;
        }

        // Second half: load cols 8..11, finish px4..7.
#pragma unroll
        for (int k = 0; k < 5; ++k) {
            float4 d = *reinterpret_cast<const float4*>(base + (size_t)k * W + 8);
            w[40 + k] = d.x; w[45 + k] = d.y; w[50 + k] = d.z; w[55 + k] = d.w;
        }

#pragma unroll
        for (int i = PROG.split; i < PROG.n; ++i) {
            const int a  = PROG.p[i].a,  b  = PROG.p[i].b;
            const int da = PROG.p[i].da, db = PROG.p[i].db;
            const int op = PROG.p[i].op;
            if (op == 0) {
                float mn = fminf(w[a], w[b]);
                float mx = fmaxf(w[a], w[b]);
                w[da] = mn;
                w[db] = mx;
            } else if (op == 1) {
                w[da] = fminf(w[a], w[b]);
            } else {
                w[db] = fmaxf(w[a], w[b]);
            }
        }

        {
            float2 s2, s3;
            s2.x = w[PROG.outslot[4]]; s2.y = w[PROG.outslot[5]];
            s3.x = w[PROG.outslot[6]]; s3.y = w[PROG.outslot[7]];
            *reinterpret_cast<float2*>(orow + x0 + 4) = s2;
            *reinterpret_cast<float2*>(orow + x0 + 6) = s3;
        }
        return;
    }

    // -------------------- Boundary path --------------------
    int idx = blk * 128 + threadIdx.x;           // 0 .. 39935
    if (idx >= 3 * 13272) return;
    int c = idx / 13272;
    int b = idx - c * 13272;

    int y, x;
    if (b < 2048) {                     // rows 0..1
        y = b >> 10; x = b & 1023;
    } else if (b < 5120) {              // rows 1021..1023
        int r = b - 2048; y = 1021 + (r >> 10); x = r & 1023;
    } else {                            // rows 2..1020, cols {0,1,1018..1023}
        int r = b - 5120;
        int q = r >> 3;
        int s = r & 7;
        y = 2 + q;
        x = (s < 2) ? s : 1016 + s;
    }

    const float* cimg = img + ((size_t)c << 20);

    float v[25];
    int inv = 0;

#pragma unroll
    for (int ky = 0; ky < 5; ++ky) {
        int yy = y + ky - 2;
        bool vy = (yy >= 0) && (yy <= H - 2);
        int  yc = min(max(yy, 0), H - 1);
        const float* row = cimg + (size_t)yc * W;
#pragma unroll
        for (int kx = 0; kx < 5; ++kx) {
            int xx = x + kx - 2;
            bool vx = (xx >= 0) && (xx <= W - 2);
            int  xc = min(max(xx, 0), W - 1);
            float val = __ldg(row + xc);
            if (!(vy && vx)) {
                val = __int_as_float((inv & 1) ? 0x7f800000u : 0xff800000u);
                ++inv;
            }
            v[ky * 5 + kx] = val;
        }
    }

#pragma unroll
    for (int i = 0; i < BNET.n; ++i) {
        const int a = BNET.p[i].a, b2 = BNET.p[i].b;
        const int op = BNET.p[i].op;
        if (op == 0) {
            float mn = fminf(v[a], v[b2]);
            float mx = fmaxf(v[a], v[b2]);
            v[a] = mn;
            v[b2] = mx;
        } else if (op == 1) {
            v[a] = fminf(v[a], v[b2]);
        } else {
            v[b2] = fmaxf(v[a], v[b2]);
        }
    }

    float s12 = v[12];
    float s13 = v[13];
    float hi  = (inv & 1) ? s13 : s12;
    out[((size_t)c << 20) + (size_t)y * W + x] = 0.5f * (s12 + hi);
}

extern "C" void kernel_launch(void* const* d_in, const int* in_sizes, int n_in,
                              void* d_out, int out_size) {
    const float* img = (const float*)d_in[0];
    float* out = (float*)d_out;
    median_fused<<<NB_BOUND + NB_INNER, 128>>>(img, out);
}